// round 13
// baseline (speedup 1.0000x reference)
#include <cuda_runtime.h>
#include <cstdint>

#define BB 2
#define SS 1024
#define CC 1024
#define HH 16
#define NBH (BB*HH)

// ---------------------------------------------------------------------------
// scratch (device globals, zero-initialized at module load; slots we never
// write stay 0 forever -> used as implicit zero padding)
// ---------------------------------------------------------------------------
__device__ float g_p[BB*SS*240];            // projection result [token][240]
// Q-side operand rows, [bh*SS + q][dims]
__device__ float g_QA1h[NBH*SS*16];  // [qrh(3), ohc(4), ohs(4), 1, ohs(4)]
__device__ float g_QA1l[NBH*SS*8];   // [qrl(3), 0...]
__device__ float g_QA2h[NBH*SS*8];   // [qdh(3), qqh, 1, 0...]
__device__ float g_QA2l[NBH*SS*8];   // [qdl(3), qql, 0...]
// K-side operand planes, [bh][dim][1024]
__device__ float g_KB1h[NBH*16*SS];  // [krh(3), 256*mask*ohc(4), c1*ohs(4), -256, c2*ohs(4)]
__device__ float g_KB1l[NBH*8*SS];   // [krl(3), 0...]
__device__ float g_KB2h[NBH*8*SS];   // [-2kdh(3), 1, kkh, 0...]
__device__ float g_KB2l[NBH*8*SS];   // [-2kdl(3), 0, kkl, 0...]
// V rows [bh][token(perm)][8] = {1, v0, v1, v2, 0...}, token permuted within
// 8-groups: j -> (j even ? j/2 : j/2+4) so PV mma needs no register shuffles
__device__ float g_KV[NBH*SS*8];
__device__ float4 g_part0[NBH*SS];   // attention partials {l, a0, a1, a2}

__device__ __forceinline__ float warp_sum(float v){
  #pragma unroll
  for (int o = 16; o > 0; o >>= 1) v += __shfl_xor_sync(0xffffffffu, v, o);
  return v;
}
__device__ __forceinline__ float fast_sqrt(float x){
  float r; asm("sqrt.approx.f32 %0, %1;" : "=f"(r) : "f"(x)); return r;
}
__device__ __forceinline__ float fast_ex2(float x){
  float r; asm("ex2.approx.f32 %0, %1;" : "=f"(r) : "f"(x)); return r;
}
__device__ __forceinline__ float softplus(float x){
  return x > 20.f ? x : log1pf(__expf(x));
}
__device__ __forceinline__ float tf32_rna(float x){
  uint32_t u; asm("cvt.rna.tf32.f32 %0, %1;" : "=r"(u) : "f"(x));
  return __uint_as_float(u);
}
__device__ __forceinline__ void split2(float x, float& h, float& l){
  h = tf32_rna(x); l = tf32_rna(x - h);
}
__device__ __forceinline__ void mma_tf32(
    float& c0, float& c1, float& c2, float& c3,
    float a0, float a1, float a2, float a3,
    float b0, float b1)
{
  asm volatile("mma.sync.aligned.m16n8k8.row.col.f32.tf32.tf32.f32 "
      "{%0,%1,%2,%3}, {%4,%5,%6,%7}, {%8,%9}, {%0,%1,%2,%3};"
      : "+f"(c0), "+f"(c1), "+f"(c2), "+f"(c3)
      : "r"(__float_as_uint(a0)), "r"(__float_as_uint(a1)),
        "r"(__float_as_uint(a2)), "r"(__float_as_uint(a3)),
        "r"(__float_as_uint(b0)), "r"(__float_as_uint(b1)));
}

// ---------------------------------------------------------------------------
// k1b: layernorm stats (prologue) + 3xTF32 mma GEMM with inline w split.
// p[r][d] = sum_c ns[r][c]*W[d][c].  BM=64, BN=64 (240 padded), BK=32.
// ---------------------------------------------------------------------------
#define KST 36
__global__ __launch_bounds__(256) void k1b_gemm(
    const float* __restrict__ s, const float* __restrict__ ln_w,
    const float* __restrict__ w_proj)
{
  __shared__ __align__(16) float Ah[64*KST];
  __shared__ __align__(16) float Al[64*KST];
  __shared__ __align__(16) float Bh[64*KST];
  __shared__ __align__(16) float Bl[64*KST];
  __shared__ float mu_s[64], rs_s[64];

  const int t   = threadIdx.x;
  const int bx  = blockIdx.x;          // n-tile 0..3
  const int by  = blockIdx.y;          // m-tile 0..31
  const int wrp = t >> 5;
  const int lane= t & 31;
  const int mw  = wrp & 3;             // m16 index
  const int nh  = wrp >> 2;            // n32 half
  const int g   = lane >> 2;           // group id
  const int tig = lane & 3;            // thread in group

  const int frow = t >> 2;             // staging row 0..63
  const int fcol = (t & 3) * 8;        // staging col group

  // ---- stats prologue: warp wrp handles rows wrp*8 .. wrp*8+7 ----
  for (int rr = 0; rr < 8; rr++) {
    int r = wrp*8 + rr;
    const float* sr = s + (size_t)(by*64 + r)*CC;
    float sum = 0.f, sq = 0.f;
    #pragma unroll
    for (int i = 0; i < 8; i++) {
      float4 v = *(const float4*)(sr + i*128 + lane*4);
      sum += v.x + v.y + v.z + v.w;
      sq  += v.x*v.x + v.y*v.y + v.z*v.z + v.w*v.w;
    }
    sum = warp_sum(sum); sq = warp_sum(sq);
    if (lane == 0) {
      float mean = sum * (1.f/CC);
      float var  = sq * (1.f/CC) - mean*mean;
      mu_s[r] = mean;
      rs_s[r] = rsqrtf(var + 1e-5f);
    }
  }

  float acc[4][4];
  #pragma unroll
  for (int j = 0; j < 4; j++)
    #pragma unroll
    for (int i = 0; i < 4; i++) acc[j][i] = 0.f;

  __syncthreads();

  for (int kc = 0; kc < 32; kc++) {
    if (kc) __syncthreads();
    // ---- stage A (normalized s) hi/lo ----
    {
      const int cg = kc*32 + fcol;
      float4 sv0 = *(const float4*)(s + (size_t)(by*64 + frow)*CC + cg);
      float4 sv1 = *(const float4*)(s + (size_t)(by*64 + frow)*CC + cg + 4);
      float4 lw0 = *(const float4*)(ln_w + cg);
      float4 lw1 = *(const float4*)(ln_w + cg + 4);
      float m_ = mu_s[frow], rr = rs_s[frow];
      float v[8] = {(sv0.x-m_)*rr*lw0.x, (sv0.y-m_)*rr*lw0.y,
                    (sv0.z-m_)*rr*lw0.z, (sv0.w-m_)*rr*lw0.w,
                    (sv1.x-m_)*rr*lw1.x, (sv1.y-m_)*rr*lw1.y,
                    (sv1.z-m_)*rr*lw1.z, (sv1.w-m_)*rr*lw1.w};
      float hv[8], lv[8];
      #pragma unroll
      for (int i = 0; i < 8; i++) split2(v[i], hv[i], lv[i]);
      *(float4*)&Ah[frow*KST + fcol]     = make_float4(hv[0],hv[1],hv[2],hv[3]);
      *(float4*)&Ah[frow*KST + fcol + 4] = make_float4(hv[4],hv[5],hv[6],hv[7]);
      *(float4*)&Al[frow*KST + fcol]     = make_float4(lv[0],lv[1],lv[2],lv[3]);
      *(float4*)&Al[frow*KST + fcol + 4] = make_float4(lv[4],lv[5],lv[6],lv[7]);
      // ---- stage B (w_proj, hi/lo split inline) ----
      int dg = bx*64 + frow;
      float4 w0 = make_float4(0.f,0.f,0.f,0.f), w1 = w0;
      if (dg < 240) {
        w0 = *(const float4*)(w_proj + (size_t)dg*CC + cg);
        w1 = *(const float4*)(w_proj + (size_t)dg*CC + cg + 4);
      }
      float wv[8] = {w0.x,w0.y,w0.z,w0.w, w1.x,w1.y,w1.z,w1.w};
      float wh[8], wl[8];
      #pragma unroll
      for (int i = 0; i < 8; i++) split2(wv[i], wh[i], wl[i]);
      *(float4*)&Bh[frow*KST + fcol]     = make_float4(wh[0],wh[1],wh[2],wh[3]);
      *(float4*)&Bh[frow*KST + fcol + 4] = make_float4(wh[4],wh[5],wh[6],wh[7]);
      *(float4*)&Bl[frow*KST + fcol]     = make_float4(wl[0],wl[1],wl[2],wl[3]);
      *(float4*)&Bl[frow*KST + fcol + 4] = make_float4(wl[4],wl[5],wl[6],wl[7]);
    }
    __syncthreads();

    // ---- mma over 4 k8 steps ----
    #pragma unroll
    for (int st = 0; st < 4; st++) {
      const int k0 = st*8;
      const int ar0 = (mw*16 + g)*KST + k0 + tig;
      const int ar1 = ar0 + 8*KST;
      float ah0 = Ah[ar0], ah1 = Ah[ar1], ah2 = Ah[ar0+4], ah3 = Ah[ar1+4];
      float al0 = Al[ar0], al1 = Al[ar1], al2 = Al[ar0+4], al3 = Al[ar1+4];
      #pragma unroll
      for (int j = 0; j < 4; j++) {
        const int br = (nh*32 + j*8 + g)*KST + k0 + tig;
        float bh0 = Bh[br], bh1 = Bh[br+4];
        float bl0 = Bl[br], bl1 = Bl[br+4];
        mma_tf32(acc[j][0], acc[j][1], acc[j][2], acc[j][3],
                 ah0, ah1, ah2, ah3, bh0, bh1);
        mma_tf32(acc[j][0], acc[j][1], acc[j][2], acc[j][3],
                 ah0, ah1, ah2, ah3, bl0, bl1);
        mma_tf32(acc[j][0], acc[j][1], acc[j][2], acc[j][3],
                 al0, al1, al2, al3, bh0, bh1);
      }
    }
  }

  const int r0 = by*64 + mw*16 + g;
  #pragma unroll
  for (int j = 0; j < 4; j++) {
    int c = bx*64 + nh*32 + j*8 + 2*tig;
    if (c < 240) {
      *(float2*)&g_p[(size_t)r0*240 + c]     = make_float2(acc[j][0], acc[j][1]);
      *(float2*)&g_p[(size_t)(r0+8)*240 + c] = make_float2(acc[j][2], acc[j][3]);
    }
  }
}

// ---------------------------------------------------------------------------
// k1c: rotate 3-vectors, fold scales, emit MMA operand planes/rows.
// block = 16 tokens, 256 threads; phase2 thread = (h, token).
// ---------------------------------------------------------------------------
__global__ __launch_bounds__(256) void k1c_scatter(
    const float* __restrict__ rot, const float* __restrict__ trans,
    const float* __restrict__ dist_scale, const float* __restrict__ rot_scale,
    const int* __restrict__ amask,
    const int* __restrict__ seq_id, const int* __restrict__ chain_id)
{
  __shared__ float p_s[16*240];
  __shared__ float rot_s[16*9];
  __shared__ float trans_s[16*3];
  __shared__ int   ch_s[16], sq_s[16], mk_s[16];
  __shared__ float rw_s[16], dw_s[16];

  const float SCL = 1.4426950408889634f / 1.7320508075688772f; // invln2/sqrt3
  const float INVLN2 = 1.4426950408889634f;
  const int tid = threadIdx.x;
  const int tb  = blockIdx.x * 16;     // 128 blocks

  for (int i = tid; i < 960; i += 256)
    *(float4*)&p_s[i*4] = *(const float4*)&g_p[(size_t)tb*240 + i*4];
  for (int i = tid; i < 144; i += 256)
    rot_s[i] = rot[(size_t)tb*9 + i];
  if (tid < 48) trans_s[tid] = trans[tb*3 + tid];
  if (tid < 16) {
    ch_s[tid] = chain_id[tb+tid];
    sq_s[tid] = seq_id[tb+tid];
    mk_s[tid] = amask[tb+tid];
    rw_s[tid] = softplus(rot_scale[tid]) * SCL;
    dw_s[tid] = softplus(dist_scale[tid]) * SCL;
  }
  __syncthreads();

  const int h = tid >> 4, tk = tid & 15;
  const int token = tb + tk;
  const int b = token >> 10, sl = token & 1023;
  const int bh = b*HH + h;
  const int qi = bh*SS + sl;
  const float* R = &rot_s[tk*9];
  const float tx = trans_s[tk*3], ty = trans_s[tk*3+1], tz = trans_s[tk*3+2];
  const float rw = rw_s[h], dw = dw_s[h];
  const int ch = ch_s[tk], sq = sq_s[tk], mk = mk_s[tk];
  const float c1b = tf32_rna(INVLN2);
  const float c2b = tf32_rna(INVLN2 - c1b);

  #define ROT3(o0,o1,o2,P) { float x=(P)[0], y=(P)[1], z=(P)[2]; \
    o0 = R[0]*x + R[1]*y + R[2]*z; \
    o1 = R[3]*x + R[4]*y + R[5]*z; \
    o2 = R[6]*x + R[7]*y + R[8]*z; }

  // ---- Q rot ----
  {
    float q0,q1,q2; ROT3(q0,q1,q2, &p_s[tk*240 + h*3]);
    q0 *= rw; q1 *= rw; q2 *= rw;
    float h0,l0,h1,l1,h2,l2;
    split2(q0,h0,l0); split2(q1,h1,l1); split2(q2,h2,l2);
    float4* A = (float4*)&g_QA1h[qi*16];
    A[0] = make_float4(h0, h1, h2, ch==0 ? 1.f:0.f);
    A[1] = make_float4(ch==1?1.f:0.f, ch==2?1.f:0.f, ch==3?1.f:0.f, sq==0?1.f:0.f);
    A[2] = make_float4(sq==1?1.f:0.f, sq==2?1.f:0.f, sq==3?1.f:0.f, 1.f);
    A[3] = make_float4(sq==0?1.f:0.f, sq==1?1.f:0.f, sq==2?1.f:0.f, sq==3?1.f:0.f);
    *(float4*)&g_QA1l[qi*8] = make_float4(l0, l1, l2, 0.f);
  }
  // ---- K rot ----
  {
    float k0,k1,k2; ROT3(k0,k1,k2, &p_s[tk*240 + (16+h)*3]);
    float h0,l0,h1,l1,h2,l2;
    split2(k0,h0,l0); split2(k1,h1,l1); split2(k2,h2,l2);
    float* P = g_KB1h + (size_t)bh*16*SS + sl;
    float mB = mk ? 256.f : 0.f;
    P[0*SS]=h0; P[1*SS]=h1; P[2*SS]=h2;
    P[3*SS] = (ch==0)?mB:0.f; P[4*SS] = (ch==1)?mB:0.f;
    P[5*SS] = (ch==2)?mB:0.f; P[6*SS] = (ch==3)?mB:0.f;
    P[7*SS] = (sq==0)?c1b:0.f; P[8*SS] = (sq==1)?c1b:0.f;
    P[9*SS] = (sq==2)?c1b:0.f; P[10*SS] = (sq==3)?c1b:0.f;
    P[11*SS] = -256.f;
    P[12*SS] = (sq==0)?c2b:0.f; P[13*SS] = (sq==1)?c2b:0.f;
    P[14*SS] = (sq==2)?c2b:0.f; P[15*SS] = (sq==3)?c2b:0.f;
    float* L = g_KB1l + (size_t)bh*8*SS + sl;
    L[0*SS]=l0; L[1*SS]=l1; L[2*SS]=l2;
  }
  // ---- V ----
  {
    float v0,v1,v2; ROT3(v0,v1,v2, &p_s[tk*240 + (32+h)*3]);
    int j = sl & 7;
    int tokp = (sl & ~7) | ((j & 1) ? (j>>1)+4 : (j>>1));
    *(float4*)&g_KV[((size_t)bh*SS + tokp)*8] =
        make_float4(1.f, tf32_rna(v0), tf32_rna(v1), tf32_rna(v2));
  }
  // ---- Q dist ----
  {
    float d0,d1,d2; ROT3(d0,d1,d2, &p_s[tk*240 + (48+h)*3]);
    d0 = (d0+tx)*dw; d1 = (d1+ty)*dw; d2 = (d2+tz)*dw;
    float qq = d0*d0 + d1*d1 + d2*d2;
    float h0,l0,h1,l1,h2,l2,hq,lq;
    split2(d0,h0,l0); split2(d1,h1,l1); split2(d2,h2,l2); split2(qq,hq,lq);
    float4* A = (float4*)&g_QA2h[qi*8];
    A[0] = make_float4(h0, h1, h2, hq);
    A[1] = make_float4(1.f, 0.f, 0.f, 0.f);
    *(float4*)&g_QA2l[qi*8] = make_float4(l0, l1, l2, lq);
  }
  // ---- K dist ----
  {
    float d0,d1,d2; ROT3(d0,d1,d2, &p_s[tk*240 + (64+h)*3]);
    d0 = (d0+tx)*dw; d1 = (d1+ty)*dw; d2 = (d2+tz)*dw;
    float kk = d0*d0 + d1*d1 + d2*d2;
    float h0,l0,h1,l1,h2,l2,hk,lk;
    split2(d0,h0,l0); split2(d1,h1,l1); split2(d2,h2,l2); split2(kk,hk,lk);
    float* P = g_KB2h + (size_t)bh*8*SS + sl;
    P[0*SS]=-2.f*h0; P[1*SS]=-2.f*h1; P[2*SS]=-2.f*h2; P[3*SS]=1.f; P[4*SS]=hk;
    float* L = g_KB2l + (size_t)bh*8*SS + sl;
    L[0*SS]=-2.f*l0; L[1*SS]=-2.f*l1; L[2*SS]=-2.f*l2; L[4*SS]=lk;
  }
  #undef ROT3
}

// ---------------------------------------------------------------------------
// k2a: tensor-core attention. block = (b, h, 64-q tile), 128 threads.
// K processed in 8 chunks of 128 tokens staged in smem.
// Per 16q x 8k tile: G1 (score+bias, 4 mma), G2 (d2, 3 mma), PV (1 mma).
// ---------------------------------------------------------------------------
__global__ __launch_bounds__(128) void k2a_attn(void)
{
  __shared__ float sB1h[16*132];
  __shared__ float sB1l[8*132];
  __shared__ float sB2h[8*132];
  __shared__ float sB2l[8*132];
  __shared__ float sV[128*8];

  const int bid = blockIdx.x;
  const int qt  = bid & 15;
  const int h   = (bid >> 4) & 15;
  const int b   = bid >> 8;
  const int tid = threadIdx.x;
  const int lane = tid & 31;
  const int w    = tid >> 5;        // 0..3
  const int g    = lane >> 2;
  const int tig  = lane & 3;

  const int bh = b*HH + h;
  const int base = bh*SS;
  const int q0 = qt*64 + w*16;

  // ---- load A fragments (per warp, fixed q rows) ----
  const float* A1h = g_QA1h + (size_t)(base)*16;
  const float* A1l = g_QA1l + (size_t)(base)*8;
  const float* A2h = g_QA2h + (size_t)(base)*8;
  const float* A2l = g_QA2l + (size_t)(base)*8;
  const int rA = q0 + g, rB = q0 + 8 + g;
  float f0a0 = A1h[rA*16+tig],   f0a1 = A1h[rB*16+tig],
        f0a2 = A1h[rA*16+tig+4], f0a3 = A1h[rB*16+tig+4];
  float f1a0 = A1h[rA*16+8+tig],   f1a1 = A1h[rB*16+8+tig],
        f1a2 = A1h[rA*16+12+tig],  f1a3 = A1h[rB*16+12+tig];
  float la0 = A1l[rA*8+tig],   la1 = A1l[rB*8+tig],
        la2 = A1l[rA*8+tig+4], la3 = A1l[rB*8+tig+4];
  float h2a0 = A2h[rA*8+tig],   h2a1 = A2h[rB*8+tig],
        h2a2 = A2h[rA*8+tig+4], h2a3 = A2h[rB*8+tig+4];
  float l2a0 = A2l[rA*8+tig],   l2a1 = A2l[rB*8+tig],
        l2a2 = A2l[rA*8+tig+4], l2a3 = A2l[rB*8+tig+4];

  float o0 = 0.f, o1 = 0.f, o2 = 0.f, o3 = 0.f;   // PV accumulator

  const float* GB1h = g_KB1h + (size_t)bh*16*SS;
  const float* GB1l = g_KB1l + (size_t)bh*8*SS;
  const float* GB2h = g_KB2h + (size_t)bh*8*SS;
  const float* GB2l = g_KB2l + (size_t)bh*8*SS;
  const float* GV   = g_KV   + (size_t)bh*SS*8;

  for (int ck = 0; ck < 8; ck++) {
    if (ck) __syncthreads();
    // ---- stage chunk (128 tokens) ----
    {
      const int c0 = ck*128;
      #pragma unroll
      for (int p = 0; p < 4; p++) {          // B1h: 16x128
        int idx = tid + p*128;
        int row = idx >> 5, col = (idx & 31)*4;
        *(float4*)&sB1h[row*132 + col] =
            *(const float4*)&GB1h[row*SS + c0 + col];
      }
      #pragma unroll
      for (int p = 0; p < 2; p++) {          // B1l, B2h, B2l: 8x128
        int idx = tid + p*128;
        int row = idx >> 5, col = (idx & 31)*4;
        *(float4*)&sB1l[row*132 + col] = *(const float4*)&GB1l[row*SS + c0 + col];
        *(float4*)&sB2h[row*132 + col] = *(const float4*)&GB2h[row*SS + c0 + col];
        *(float4*)&sB2l[row*132 + col] = *(const float4*)&GB2l[row*SS + c0 + col];
      }
      #pragma unroll
      for (int p = 0; p < 2; p++) {          // V: 128x8
        int idx = (tid + p*128)*4;
        *(float4*)&sV[idx] = *(const float4*)&GV[c0*8 + idx];
      }
    }
    __syncthreads();

    #pragma unroll 2
    for (int n0 = 0; n0 < 16; n0++) {
      const int col = n0*8 + g;
      float b1h0 = sB1h[tig*132 + col],     b1h1 = sB1h[(tig+4)*132 + col];
      float b1h2 = sB1h[(8+tig)*132 + col], b1h3 = sB1h[(12+tig)*132 + col];
      float b1l0 = sB1l[tig*132 + col],     b1l1 = sB1l[(tig+4)*132 + col];
      float b2h0 = sB2h[tig*132 + col],     b2h1 = sB2h[(tig+4)*132 + col];
      float b2l0 = sB2l[tig*132 + col],     b2l1 = sB2l[(tig+4)*132 + col];
      float bv0  = sV[(n0*8+tig)*8 + g],    bv1  = sV[(n0*8+tig+4)*8 + g];

      float s0=0.f, s1=0.f, s2=0.f, s3=0.f;       // G1: score + bias
      mma_tf32(s0,s1,s2,s3, f0a0,f0a1,f0a2,f0a3, b1h0,b1h1);
      mma_tf32(s0,s1,s2,s3, f1a0,f1a1,f1a2,f1a3, b1h2,b1h3);
      mma_tf32(s0,s1,s2,s3, la0,la1,la2,la3,     b1h0,b1h1);
      mma_tf32(s0,s1,s2,s3, f0a0,f0a1,f0a2,f0a3, b1l0,b1l1);
      float d0=0.f, d1=0.f, d2=0.f, d3=0.f;       // G2: d2
      mma_tf32(d0,d1,d2,d3, h2a0,h2a1,h2a2,h2a3, b2h0,b2h1);
      mma_tf32(d0,d1,d2,d3, h2a0,h2a1,h2a2,h2a3, b2l0,b2l1);
      mma_tf32(d0,d1,d2,d3, l2a0,l2a1,l2a2,l2a3, b2h0,b2h1);

      float p0 = tf32_rna(fast_ex2(s0 - fast_sqrt(fmaxf(d0, 0.f))));
      float p1 = tf32_rna(fast_ex2(s1 - fast_sqrt(fmaxf(d1, 0.f))));
      float p2 = tf32_rna(fast_ex2(s2 - fast_sqrt(fmaxf(d2, 0.f))));
      float p3 = tf32_rna(fast_ex2(s3 - fast_sqrt(fmaxf(d3, 0.f))));

      // PV: A-frag from C-frag via permuted V rows: (a0,a1,a2,a3)=(p0,p2,p1,p3)
      mma_tf32(o0,o1,o2,o3, p0,p2,p1,p3, bv0,bv1);
    }
  }

  // ---- epilogue: cols {0,1}=l,a0 (tig=0); {2,3}=a1,a2 (tig=1) ----
  if (tig < 2) {
    float* P = (float*)&g_part0[base + q0 + g];
    P[tig*2] = o0; P[tig*2+1] = o1;
    float* Q = (float*)&g_part0[base + q0 + 8 + g];
    Q[tig*2] = o2; Q[tig*2+1] = o3;
  }
}

// ---------------------------------------------------------------------------
// k3: fused normalize + back-rotation + mask + output GEMM.
// ---------------------------------------------------------------------------
__global__ __launch_bounds__(256) void k3_out(
    const float* __restrict__ rot, const int* __restrict__ amask,
    const float* __restrict__ w_out, float* __restrict__ out)
{
  __shared__ float w_s[48*64];    // [d][c]
  __shared__ float a_s[48*128];   // [d][r]
  __shared__ float rot_s[128*9];
  const int tid = threadIdx.x;
  const int ct = blockIdx.x & 15, st = blockIdx.x >> 4;
  const int cb = ct*64, sb = st*128;

  for (int idx = tid; idx < 64*48; idx += 256) {
    int c = idx/48, d = idx - c*48;
    w_s[d*64 + c] = w_out[(size_t)(cb + c)*48 + d];
  }
  for (int idx = tid; idx < 128*9; idx += 256)
    rot_s[idx] = rot[(size_t)sb*9 + idx];
  __syncthreads();

  for (int i = tid; i < 128*16; i += 256) {
    int r = i & 127, h = i >> 7;
    int row = sb + r;
    int b = row >> 10, q = row & 1023;
    int idx = ((b*HH + h) << 10) + q;
    float4 p0 = g_part0[idx];
    float inv = 1.f / p0.x;
    float o0 = p0.y * inv;
    float o1 = p0.z * inv;
    float o2 = p0.w * inv;
    const float* R = &rot_s[r*9];
    float mk = (amask[row] != 0) ? 1.f : 0.f;
    a_s[(h*3+0)*128 + r] = (R[0]*o0 + R[3]*o1 + R[6]*o2) * mk;
    a_s[(h*3+1)*128 + r] = (R[1]*o0 + R[4]*o1 + R[7]*o2) * mk;
    a_s[(h*3+2)*128 + r] = (R[2]*o0 + R[5]*o1 + R[8]*o2) * mk;
  }
  __syncthreads();

  const int tx = tid & 15, ty = tid >> 4;
  float acc[8][4];
  #pragma unroll
  for (int i = 0; i < 8; i++)
    #pragma unroll
    for (int j = 0; j < 4; j++) acc[i][j] = 0.f;

  #pragma unroll 4
  for (int d = 0; d < 48; d++) {
    float4 wv = *(const float4*)&w_s[d*64 + tx*4];
    float4 aA = *(const float4*)&a_s[d*128 + ty*8];
    float4 aB = *(const float4*)&a_s[d*128 + ty*8 + 4];
    float av[8] = {aA.x, aA.y, aA.z, aA.w, aB.x, aB.y, aB.z, aB.w};
    #pragma unroll
    for (int i = 0; i < 8; i++) {
      acc[i][0] += av[i]*wv.x;
      acc[i][1] += av[i]*wv.y;
      acc[i][2] += av[i]*wv.z;
      acc[i][3] += av[i]*wv.w;
    }
  }
  #pragma unroll
  for (int i = 0; i < 8; i++) {
    float4 res = make_float4(acc[i][0], acc[i][1], acc[i][2], acc[i][3]);
    *(float4*)&out[(size_t)(sb + ty*8 + i)*1024 + cb + tx*4] = res;
  }
}

// ---------------------------------------------------------------------------
extern "C" void kernel_launch(void* const* d_in, const int* in_sizes, int n_in,
                              void* d_out, int out_size)
{
  const float* s          = (const float*)d_in[0];
  const float* rot        = (const float*)d_in[1];
  const float* trans      = (const float*)d_in[2];
  const float* ln_w       = (const float*)d_in[3];
  const float* w_proj     = (const float*)d_in[4];
  const float* w_out      = (const float*)d_in[5];
  const float* dist_scale = (const float*)d_in[6];
  const float* rot_scale  = (const float*)d_in[7];
  const int* am           = (const int*)d_in[8];
  const int* seq_id       = (const int*)d_in[9];
  const int* chain_id     = (const int*)d_in[10];
  float* out = (float*)d_out;

  k1b_gemm   <<<dim3(4,32), 256>>>(s, ln_w, w_proj);
  k1c_scatter<<<128, 256>>>(rot, trans, dist_scale, rot_scale, am, seq_id, chain_id);
  k2a_attn   <<<512, 128>>>();
  k3_out     <<<256, 256>>>(rot, am, w_out, out);
}